// round 2
// baseline (speedup 1.0000x reference)
#include <cuda_runtime.h>
#include <stdint.h>
#include <math.h>

// CounterfactualDiffusion: 50-step diffusion sampler, persistent kernel.
// Each CTA owns MTILE=64 batch rows for all 50 steps (rows are independent).
#define BATCH    8192
#define LAT      128
#define HID      512
#define NSTEPS   50
#define MTILE    64
#define NTHREADS 512
#define NCTAS    (BATCH / MTILE)   // 128
#define ACTSTR   512
#define KCL      16

// ---------------- JAX threefry-2x32 (exact) ----------------
__device__ __forceinline__ uint32_t rotl32(uint32_t x, uint32_t r) {
    return __funnelshift_l(x, x, r);
}

__device__ __forceinline__ void threefry2x32(uint32_t k0, uint32_t k1,
                                             uint32_t c0, uint32_t c1,
                                             uint32_t& o0, uint32_t& o1) {
    uint32_t ks2 = k0 ^ k1 ^ 0x1BD11BDAu;
    uint32_t x0 = c0 + k0;
    uint32_t x1 = c1 + k1;
#define TF_RND(r) { x0 += x1; x1 = rotl32(x1, r); x1 ^= x0; }
    TF_RND(13) TF_RND(15) TF_RND(26) TF_RND(6)
    x0 += k1;  x1 += ks2 + 1u;
    TF_RND(17) TF_RND(29) TF_RND(16) TF_RND(24)
    x0 += ks2; x1 += k0 + 2u;
    TF_RND(13) TF_RND(15) TF_RND(26) TF_RND(6)
    x0 += k0;  x1 += k1 + 3u;
    TF_RND(17) TF_RND(29) TF_RND(16) TF_RND(24)
    x0 += k1;  x1 += ks2 + 4u;
    TF_RND(13) TF_RND(15) TF_RND(26) TF_RND(6)
    x0 += ks2; x1 += k0 + 5u;
#undef TF_RND
    o0 = x0; o1 = x1;
}

// XLA f32 erf_inv (Giles polynomial) — matches lax.erf_inv
__device__ __forceinline__ float erfinv_f32(float x) {
    float w = -log1pf(-x * x);
    float p;
    if (w < 5.0f) {
        w -= 2.5f;
        p = 2.81022636e-08f;
        p = fmaf(p, w, 3.43273939e-07f);
        p = fmaf(p, w, -3.5233877e-06f);
        p = fmaf(p, w, -4.39150654e-06f);
        p = fmaf(p, w, 0.00021858087f);
        p = fmaf(p, w, -0.00125372503f);
        p = fmaf(p, w, -0.00417768164f);
        p = fmaf(p, w, 0.246640727f);
        p = fmaf(p, w, 1.50140941f);
    } else {
        w = sqrtf(w) - 3.0f;
        p = -0.000200214257f;
        p = fmaf(p, w, 0.000100950558f);
        p = fmaf(p, w, 0.00134934322f);
        p = fmaf(p, w, -0.00367342844f);
        p = fmaf(p, w, 0.00573950773f);
        p = fmaf(p, w, -0.0076224613f);
        p = fmaf(p, w, 0.00943887047f);
        p = fmaf(p, w, 1.00167406f);
        p = fmaf(p, w, 2.83297682f);
    }
    return p * x;
}

// JAX partitionable-threefry normal sample for flat element index gi at step t.
// bits = o0 ^ o1 of threefry(folded_key, (0, gi)); u in [-0.99999994, 1);
// normal = sqrt(2) * erfinv(u).
__device__ __forceinline__ float jax_normal(uint32_t fk0, uint32_t fk1, uint32_t gi) {
    uint32_t o0, o1;
    threefry2x32(fk0, fk1, 0u, gi, o0, o1);
    uint32_t bits = o0 ^ o1;
    float f = __uint_as_float((bits >> 9) | 0x3f800000u) - 1.0f;
    // (hi - lo) rounds to exactly 2.0f in f32; mul-by-2 is exact.
    float u = fmaxf(fmaf(f, 2.0f, -0.99999994f), -0.99999994f);
    return 1.4142135623730951f * erfinv_f32(u);
}

__device__ __forceinline__ float gelu_exact(float v) {
    return 0.5f * v * (1.0f + erff(v * 0.7071067811865476f));
}

// ---------------- GEMM micro-tile ----------------
// Each thread: 4 rows (rg*4..+3) x NJ cols (cg + 32*j).  W tile staged in SMEM.
template<int K, int N, int NJ>
__device__ __forceinline__ void dense_layer(const float* __restrict__ W,
                                            const float* sA, float* sW,
                                            float acc[4][NJ],
                                            int tid, int cg, int rg) {
    for (int kb = 0; kb < K; kb += KCL) {
        __syncthreads();
        const float4* gw = reinterpret_cast<const float4*>(W + kb * N);
        float4* sw4 = reinterpret_cast<float4*>(sW);
        constexpr int NVEC = (KCL * N / 4) / NTHREADS;
#pragma unroll
        for (int v = 0; v < NVEC; ++v)
            sw4[v * NTHREADS + tid] = gw[v * NTHREADS + tid];
        __syncthreads();
        const float* a0 = sA + (rg * 4 + 0) * ACTSTR + kb;
        const float* a1 = a0 + ACTSTR;
        const float* a2 = a1 + ACTSTR;
        const float* a3 = a2 + ACTSTR;
#pragma unroll 8
        for (int k = 0; k < KCL; ++k) {
            float v0 = a0[k], v1 = a1[k], v2 = a2[k], v3 = a3[k];
            const float* wr = sW + k * N + cg;
#pragma unroll
            for (int j = 0; j < NJ; ++j) {
                float w = wr[32 * j];
                acc[0][j] = fmaf(v0, w, acc[0][j]);
                acc[1][j] = fmaf(v1, w, acc[1][j]);
                acc[2][j] = fmaf(v2, w, acc[2][j]);
                acc[3][j] = fmaf(v3, w, acc[3][j]);
            }
        }
    }
}

__global__ void __launch_bounds__(NTHREADS, 1)
diffusion_kernel(const float* __restrict__ condition,
                 const float* __restrict__ x_init,
                 const float* __restrict__ W1, const float* __restrict__ b1,
                 const float* __restrict__ W2, const float* __restrict__ b2,
                 const float* __restrict__ W3, const float* __restrict__ b3,
                 const float* __restrict__ W4, const float* __restrict__ b4,
                 const int* __restrict__ tsp,
                 float* __restrict__ out)
{
    extern __shared__ float smem[];
    float* sA = smem;                    // [64][512] activations
    float* sW = smem + MTILE * ACTSTR;   // [KCL][512] weight tile

    __shared__ float s_c1[NSTEPS], s_isa[NSTEPS], s_sb[NSTEPS];

    int tid = threadIdx.x;
    int cg = tid & 31;
    int rg = tid >> 5;
    int row0 = blockIdx.x * MTILE + rg * 4;

    if (tid == 0) {
        // betas = linspace(1e-4, 0.02, 50), f32; cumprod f32 (matches jnp)
        float acp = 1.0f;
        float bstep = (0.02f - 1e-4f) / 49.0f;
        for (int t = 0; t < NSTEPS; ++t) {
            float beta = fmaf((float)t, bstep, 1e-4f);
            float alpha = 1.0f - beta;
            acp *= alpha;
            s_c1[t]  = beta / sqrtf(1.0f - acp);
            s_isa[t] = 1.0f / sqrtf(alpha);
            s_sb[t]  = sqrtf(beta);
        }
    }

    float xr[4][4];
#pragma unroll
    for (int i = 0; i < 4; ++i)
#pragma unroll
        for (int j = 0; j < 4; ++j)
            xr[i][j] = x_init[(row0 + i) * LAT + cg + 32 * j];

    float tgt = (*tsp) ? 0.0f : 1.0f;   // target column value

    for (int t = NSTEPS - 1; t >= 0; --t) {
        // Build input tile [x | condition]; t_emb/target columns are row-
        // constant and folded into layer-1's bias, so effective K=256.
#pragma unroll
        for (int i = 0; i < 4; ++i) {
            float* arow = sA + (rg * 4 + i) * ACTSTR;
            const float* crow = condition + (row0 + i) * LAT;
#pragma unroll
            for (int j = 0; j < 4; ++j) {
                int c = cg + 32 * j;
                arow[c] = xr[i][j];
                arow[LAT + c] = crow[c];
            }
        }
        float tval = (float)t / (float)NSTEPS;

        {   // layer 1: 256 -> 512, gelu
            float acc[4][16];
#pragma unroll
            for (int j = 0; j < 16; ++j) {
                int c = cg + 32 * j;
                float bb = b1[c] + tval * W1[256 * HID + c] + tgt * W1[257 * HID + c];
                acc[0][j] = bb; acc[1][j] = bb; acc[2][j] = bb; acc[3][j] = bb;
            }
            dense_layer<256, 512, 16>(W1, sA, sW, acc, tid, cg, rg);
            __syncthreads();
#pragma unroll
            for (int i = 0; i < 4; ++i) {
                float* arow = sA + (rg * 4 + i) * ACTSTR;
#pragma unroll
                for (int j = 0; j < 16; ++j)
                    arow[cg + 32 * j] = gelu_exact(acc[i][j]);
            }
        }
        {   // layer 2: 512 -> 512, gelu
            float acc[4][16];
#pragma unroll
            for (int j = 0; j < 16; ++j) {
                float bb = b2[cg + 32 * j];
                acc[0][j] = bb; acc[1][j] = bb; acc[2][j] = bb; acc[3][j] = bb;
            }
            dense_layer<512, 512, 16>(W2, sA, sW, acc, tid, cg, rg);
            __syncthreads();
#pragma unroll
            for (int i = 0; i < 4; ++i) {
                float* arow = sA + (rg * 4 + i) * ACTSTR;
#pragma unroll
                for (int j = 0; j < 16; ++j)
                    arow[cg + 32 * j] = gelu_exact(acc[i][j]);
            }
        }
        {   // layer 3: 512 -> 512, gelu
            float acc[4][16];
#pragma unroll
            for (int j = 0; j < 16; ++j) {
                float bb = b3[cg + 32 * j];
                acc[0][j] = bb; acc[1][j] = bb; acc[2][j] = bb; acc[3][j] = bb;
            }
            dense_layer<512, 512, 16>(W3, sA, sW, acc, tid, cg, rg);
            __syncthreads();
#pragma unroll
            for (int i = 0; i < 4; ++i) {
                float* arow = sA + (rg * 4 + i) * ACTSTR;
#pragma unroll
                for (int j = 0; j < 16; ++j)
                    arow[cg + 32 * j] = gelu_exact(acc[i][j]);
            }
        }
        float np4[4][4];
        {   // layer 4: 512 -> 128, linear
            float acc[4][4];
#pragma unroll
            for (int j = 0; j < 4; ++j) {
                float bb = b4[cg + 32 * j];
                acc[0][j] = bb; acc[1][j] = bb; acc[2][j] = bb; acc[3][j] = bb;
            }
            dense_layer<512, 128, 4>(W4, sA, sW, acc, tid, cg, rg);
            __syncthreads();   // all sA reads done before next step's writes
#pragma unroll
            for (int i = 0; i < 4; ++i)
#pragma unroll
                for (int j = 0; j < 4; ++j)
                    np4[i][j] = acc[i][j];
        }

        // x update with JAX-exact noise (partitionable threefry).
        uint32_t fk0, fk1;
        threefry2x32(0u, 42u, 0u, (uint32_t)t, fk0, fk1);  // fold_in(key(42), t)
        float c1 = s_c1[t], isa = s_isa[t], sb = s_sb[t];
#pragma unroll
        for (int i = 0; i < 4; ++i) {
            int grow = row0 + i;
#pragma unroll
            for (int j = 0; j < 4; ++j) {
                float nz = 0.0f;
                if (t > 0) {
                    uint32_t gi = (uint32_t)(grow * LAT + cg + 32 * j);
                    nz = jax_normal(fk0, fk1, gi);
                }
                xr[i][j] = (xr[i][j] - c1 * np4[i][j]) * isa + sb * nz;
            }
        }
    }

#pragma unroll
    for (int i = 0; i < 4; ++i)
#pragma unroll
        for (int j = 0; j < 4; ++j)
            out[(row0 + i) * LAT + cg + 32 * j] = xr[i][j];
}

extern "C" void kernel_launch(void* const* d_in, const int* in_sizes, int n_in,
                              void* d_out, int out_size) {
    const float* condition = (const float*)d_in[0];
    const float* x_init    = (const float*)d_in[1];
    const float* W1 = (const float*)d_in[2];
    const float* b1 = (const float*)d_in[3];
    const float* W2 = (const float*)d_in[4];
    const float* b2 = (const float*)d_in[5];
    const float* W3 = (const float*)d_in[6];
    const float* b3 = (const float*)d_in[7];
    const float* W4 = (const float*)d_in[8];
    const float* b4 = (const float*)d_in[9];
    const int*   ts = (const int*)d_in[10];
    float* out = (float*)d_out;

    const int smem_bytes = (MTILE * ACTSTR + KCL * HID) * (int)sizeof(float); // 163840
    cudaFuncSetAttribute(diffusion_kernel,
                         cudaFuncAttributeMaxDynamicSharedMemorySize, smem_bytes);
    diffusion_kernel<<<NCTAS, NTHREADS, smem_bytes>>>(
        condition, x_init, W1, b1, W2, b2, W3, b3, W4, b4, ts, out);
}